// round 3
// baseline (speedup 1.0000x reference)
#include <cuda_runtime.h>
#include <math.h>

#define H 128
#define DIN 132
#define NN 2048              // N (nodes per graph)
#define NMASK 2047u
#define E_MAX 1000000
#define TE 32                // edges per tile
#define T1 128               // threads in gemm kernel

// scratch: h [E,128] fp32 (512MB), stats, folded BN params
__device__ float g_h[(size_t)E_MAX * H];
__device__ float g_sum[H];
__device__ float g_sq[H];
__device__ float g_A[H];
__device__ float g_B[H];

// smem layout (floats): W1s[DIN*H] | xs[DIN*TE] | bsum[H] | bsq[H] | sidx[32] didx[32] (as int)
#define SMEM_FLOATS (DIN*H + DIN*TE + 2*H + 64)
#define SMEM_BYTES (SMEM_FLOATS * 4)

__global__ void init_stats_kernel() {
    int t = threadIdx.x;
    if (t < H) { g_sum[t] = 0.f; g_sq[t] = 0.f; }
}

__global__ void __launch_bounds__(T1) edge_gemm_kernel(
    const float* __restrict__ zf,       // [B*N, 64]
    const float* __restrict__ ea,       // [E, 4]
    const float* __restrict__ W1,       // [132, 128]
    const float* __restrict__ b1,       // [128]
    const int* __restrict__ eidx,       // [2, E]  (int32! JAX x64 disabled)
    int E, int BN)                      // BN = B*N
{
    extern __shared__ float smem[];
    float* W1s  = smem;                 // DIN*H
    float* xs   = smem + DIN * H;       // DIN*TE, layout [k][e]
    float* bsum = xs + DIN * TE;        // H
    float* bsq  = bsum + H;             // H
    int*   sidx = (int*)(bsq + H);      // 32
    int*   didx = sidx + 32;            // 32

    const int tid = threadIdx.x;

    // load W1 into smem (vectorized)
    for (int i = tid; i < DIN * H / 4; i += T1)
        ((float4*)W1s)[i] = ((const float4*)W1)[i];
    bsum[tid] = 0.f;
    bsq[tid]  = 0.f;

    const int ebase = blockIdx.x * TE;
    const int Bm1 = BN / NN - 1;

    // resolve indices per reference:
    //   batch = clip(src / N, 0, B-1); off = batch*N
    //   src_idx = src % N + off ; dst_idx = dst % N + off
    if (tid < TE) {
        int e = ebase + tid;
        int s = 0, d = 0;
        if (e < E) {
            s = eidx[e];
            d = eidx[(size_t)E + e];
        }
        int batch = s >> 11;               // src / 2048 (src >= 0)
        batch = max(0, min(batch, Bm1));
        int off = batch << 11;
        int si = (int)((unsigned)s & NMASK) + off;
        int di = (int)((unsigned)d & NMASK) + off;
        sidx[tid] = si;
        didx[tid] = di;
    }
    __syncthreads();

    // gather edge inputs into xs[k][e] (transposed): thread = (part, e)
    {
        const int e = tid & 31;
        const int valid = (ebase + e) < E;
        const float* zs = zf + (size_t)sidx[e] * 64;
        const float* zd = zf + (size_t)didx[e] * 64;
        const float* at = ea + (size_t)(ebase + e) * 4;
        for (int k = tid >> 5; k < DIN; k += 4) {
            float v = 0.f;
            if (valid) {
                if (k < 64)       v = zs[k];
                else if (k < 128) v = zd[k - 64];
                else              v = at[k - 128];
            }
            xs[k * TE + e] = v;
        }
    }
    __syncthreads();

    // thread tile: 4 edges x 8 channels. cg in [0,16), eg in [0,8)
    // channels: c0 = cg*4 .. +3 and c1 = 64 + cg*4 .. +3 (bank-conflict-free LDS.128)
    const int cg = tid & 15;
    const int eg = tid >> 4;
    const int c0 = cg * 4;
    const int c1 = 64 + cg * 4;

    float acc[4][8];
#pragma unroll
    for (int i = 0; i < 4; i++)
#pragma unroll
        for (int j = 0; j < 8; j++) acc[i][j] = 0.f;

#pragma unroll 4
    for (int k = 0; k < DIN; k++) {
        const float4 xv = *(const float4*)&xs[k * TE + eg * 4];
        const float4 w0 = *(const float4*)&W1s[k * H + c0];
        const float4 w1 = *(const float4*)&W1s[k * H + c1];
        const float xr[4] = {xv.x, xv.y, xv.z, xv.w};
        const float wr[8] = {w0.x, w0.y, w0.z, w0.w, w1.x, w1.y, w1.z, w1.w};
#pragma unroll
        for (int i = 0; i < 4; i++)
#pragma unroll
            for (int j = 0; j < 8; j++)
                acc[i][j] = fmaf(xr[i], wr[j], acc[i][j]);
    }

    // bias
    const float4 bv0 = *(const float4*)&b1[c0];
    const float4 bv1 = *(const float4*)&b1[c1];
    const float br[8] = {bv0.x, bv0.y, bv0.z, bv0.w, bv1.x, bv1.y, bv1.z, bv1.w};
#pragma unroll
    for (int i = 0; i < 4; i++)
#pragma unroll
        for (int j = 0; j < 8; j++) acc[i][j] += br[j];

    // store h + accumulate per-channel stats
    float s0[8], s1[8];
#pragma unroll
    for (int j = 0; j < 8; j++) { s0[j] = 0.f; s1[j] = 0.f; }

#pragma unroll
    for (int i = 0; i < 4; i++) {
        int e = ebase + eg * 4 + i;
        if (e < E) {
            float4 o0 = make_float4(acc[i][0], acc[i][1], acc[i][2], acc[i][3]);
            float4 o1 = make_float4(acc[i][4], acc[i][5], acc[i][6], acc[i][7]);
            *(float4*)&g_h[(size_t)e * H + c0] = o0;
            *(float4*)&g_h[(size_t)e * H + c1] = o1;
#pragma unroll
            for (int j = 0; j < 8; j++) {
                s0[j] += acc[i][j];
                s1[j] += acc[i][j] * acc[i][j];
            }
        }
    }

    // reduce over eg-bit0 (lane^16 is same cg, adjacent eg)
#pragma unroll
    for (int j = 0; j < 8; j++) {
        s0[j] += __shfl_xor_sync(0xffffffffu, s0[j], 16);
        s1[j] += __shfl_xor_sync(0xffffffffu, s1[j], 16);
    }
    if ((tid & 16) == 0) {
#pragma unroll
        for (int j = 0; j < 4; j++) {
            atomicAdd(&bsum[c0 + j], s0[j]);
            atomicAdd(&bsq [c0 + j], s1[j]);
            atomicAdd(&bsum[c1 + j], s0[4 + j]);
            atomicAdd(&bsq [c1 + j], s1[4 + j]);
        }
    }
    __syncthreads();
    if (tid < H) {
        atomicAdd(&g_sum[tid], bsum[tid]);
        atomicAdd(&g_sq [tid], bsq[tid]);
    }
}

__global__ void finalize_stats_kernel(const float* __restrict__ gamma,
                                      const float* __restrict__ beta,
                                      float invE)
{
    int c = threadIdx.x;
    if (c < H) {
        float mu  = g_sum[c] * invE;
        float var = g_sq[c] * invE - mu * mu;
        float inv = rsqrtf(var + 1e-5f);
        float A = gamma[c] * inv;
        g_A[c] = A;
        g_B[c] = beta[c] - mu * A;
    }
}

// one warp per edge: read h row (512B coalesced), BN affine + LeakyReLU + dot W2
__global__ void __launch_bounds__(256) out_kernel(
    const float* __restrict__ W2,
    const float* __restrict__ b2,
    float* __restrict__ out,
    int E)
{
    const int gwarp = (blockIdx.x * blockDim.x + threadIdx.x) >> 5;
    const int lane  = threadIdx.x & 31;
    if (gwarp >= E) return;

    const float4 A  = ((const float4*)g_A)[lane];
    const float4 Bv = ((const float4*)g_B)[lane];
    const float4 w  = ((const float4*)W2)[lane];
    const float4 h  = *(const float4*)&g_h[(size_t)gwarp * H + lane * 4];

    float r = 0.f;
    {
        float t;
        t = h.x * A.x + Bv.x; t = (t >= 0.f) ? t : 0.2f * t; r += t * w.x;
        t = h.y * A.y + Bv.y; t = (t >= 0.f) ? t : 0.2f * t; r += t * w.y;
        t = h.z * A.z + Bv.z; t = (t >= 0.f) ? t : 0.2f * t; r += t * w.z;
        t = h.w * A.w + Bv.w; t = (t >= 0.f) ? t : 0.2f * t; r += t * w.w;
    }
#pragma unroll
    for (int o = 16; o > 0; o >>= 1)
        r += __shfl_xor_sync(0xffffffffu, r, o);
    if (lane == 0) out[gwarp] = r + b2[0];
}

extern "C" void kernel_launch(void* const* d_in, const int* in_sizes, int n_in,
                              void* d_out, int out_size)
{
    const float* z     = (const float*)d_in[0];
    const float* ea    = (const float*)d_in[1];
    const float* W1    = (const float*)d_in[2];
    const float* b1    = (const float*)d_in[3];
    const float* gamma = (const float*)d_in[4];
    const float* beta  = (const float*)d_in[5];
    const float* W2    = (const float*)d_in[6];
    const float* b2    = (const float*)d_in[7];
    const int*   eidx  = (const int*)d_in[8];     // int32 (JAX x64 disabled)

    const int E  = in_sizes[1] / 4;   // edge_attr is [E,4]
    const int BN = in_sizes[0] / 64;  // z is [B, N, 64]
    float* out = (float*)d_out;

    cudaFuncSetAttribute(edge_gemm_kernel,
                         cudaFuncAttributeMaxDynamicSharedMemorySize, SMEM_BYTES);

    init_stats_kernel<<<1, 128>>>();
    edge_gemm_kernel<<<(E + TE - 1) / TE, T1, SMEM_BYTES>>>(z, ea, W1, b1, eidx, E, BN);
    finalize_stats_kernel<<<1, 128>>>(gamma, beta, 1.0f / (float)E);
    out_kernel<<<(E + 7) / 8, 256>>>(W2, b2, out, E);
}

// round 4
// speedup vs baseline: 6.6910x; 6.6910x over previous
#include <cuda_runtime.h>
#include <math.h>

#define H 128
#define NMASK 2047           // N = 2048
#define BN_MAX 65536
#define FULL 0xffffffffu

// P[n][0:128] = zf[n] @ W1[0:64,:] ; P[n][128:256] = zf[n] @ W1[64:128,:]
__device__ float g_P[(size_t)BN_MAX * 256];
__device__ float g_sum[H];
__device__ float g_sq[H];
__device__ float g_A[H];
__device__ float g_B[H];

__global__ void init_stats_kernel() {
    int t = threadIdx.x;
    if (t < H) { g_sum[t] = 0.f; g_sq[t] = 0.f; }
}

// ---------------- node GEMM: P[BN,256] = zf[BN,64] @ Wc[64,256] ----------------
// tile: 64 nodes x 256 cols per block, 256 threads, thread = 8 nodes x 8 cols
#define NG_SMEM ((64*256 + 64*64) * 4)
__global__ void __launch_bounds__(256) node_gemm_kernel(
    const float* __restrict__ zf,   // [BN, 64]
    const float* __restrict__ W1,   // [132, 128]
    int BN)
{
    extern __shared__ float smem[];
    float* Wc = smem;               // [64][256]
    float* xs = smem + 64 * 256;    // [64 nodes][64 k]

    const int tid = threadIdx.x;
    const int nb = blockIdx.x * 64;

    // Wc[k][c] = W1[k][c] (c<128) else W1[64+k][c-128]
    const float4* W1f4 = (const float4*)W1;   // row = 32 float4
#pragma unroll
    for (int it = 0; it < 16; it++) {
        int i = tid + it * 256;                // float4 index into Wc
        int k = i >> 6, c4 = i & 63;
        ((float4*)Wc)[i] = (c4 < 32) ? W1f4[k * 32 + c4]
                                     : W1f4[(64 + k) * 32 + (c4 - 32)];
    }
    // xs[node][k] direct copy (coalesced)
#pragma unroll
    for (int it = 0; it < 4; it++) {
        int i = tid + it * 256;                // float4 index
        int node = i >> 4, k4 = i & 15;
        int nn = min(nb + node, BN - 1);
        ((float4*)xs)[node * 16 + k4] = *(const float4*)&zf[(size_t)nn * 64 + k4 * 4];
    }
    __syncthreads();

    const int cg = tid & 31;       // col group: c0 = cg*4 (0..124), c1 = 128+cg*4
    const int ng = tid >> 5;       // node group: nodes ng*8 .. ng*8+7 (uniform per warp)
    const int c0 = cg * 4;
    const int c1 = 128 + cg * 4;

    float acc[8][8];
#pragma unroll
    for (int i = 0; i < 8; i++)
#pragma unroll
        for (int j = 0; j < 8; j++) acc[i][j] = 0.f;

#pragma unroll 4
    for (int k = 0; k < 64; k++) {
        float xk[8];
#pragma unroll
        for (int i = 0; i < 8; i++) xk[i] = xs[(ng * 8 + i) * 64 + k];  // broadcast
        const float4 w0 = *(const float4*)&Wc[k * 256 + c0];
        const float4 w1 = *(const float4*)&Wc[k * 256 + c1];
        const float wr[8] = {w0.x, w0.y, w0.z, w0.w, w1.x, w1.y, w1.z, w1.w};
#pragma unroll
        for (int i = 0; i < 8; i++)
#pragma unroll
            for (int j = 0; j < 8; j++)
                acc[i][j] = fmaf(xk[i], wr[j], acc[i][j]);
    }

#pragma unroll
    for (int i = 0; i < 8; i++) {
        int node = nb + ng * 8 + i;
        if (node < BN) {
            *(float4*)&g_P[(size_t)node * 256 + c0] =
                make_float4(acc[i][0], acc[i][1], acc[i][2], acc[i][3]);
            *(float4*)&g_P[(size_t)node * 256 + c1] =
                make_float4(acc[i][4], acc[i][5], acc[i][6], acc[i][7]);
        }
    }
}

// ---------------- pass A: gather + h recompute + BN stats ----------------
__global__ void __launch_bounds__(256) pass_a_kernel(
    const float* __restrict__ ea,   // [E,4]
    const float* __restrict__ W1,   // [132,128]
    const float* __restrict__ b1,
    const int* __restrict__ eidx,   // [2,E] int32
    int E, int Bm1)
{
    __shared__ float bsum[H], bsq[H];
    const int tid = threadIdx.x;
    const int lane = tid & 31;
    const int wrp = tid >> 5;
    if (tid < H) { bsum[tid] = 0.f; bsq[tid] = 0.f; }
    __syncthreads();

    const int c = lane * 4;
    // W1 attr rows (128..131) for this lane's 4 channels
    float w1a[4][4];
#pragma unroll
    for (int k = 0; k < 4; k++) {
        float4 v = *(const float4*)&W1[(128 + k) * H + c];
        w1a[k][0] = v.x; w1a[k][1] = v.y; w1a[k][2] = v.z; w1a[k][3] = v.w;
    }
    const float4 b1v = *(const float4*)&b1[c];

    float s0 = 0.f, s1 = 0.f, s2 = 0.f, s3 = 0.f;
    float q0 = 0.f, q1 = 0.f, q2 = 0.f, q3 = 0.f;

    const int nwarps = gridDim.x * 8;
    const int gw = blockIdx.x * 8 + wrp;
    const int nchunks = (E + 31) >> 5;

    for (int ch = gw; ch < nchunks; ch += nwarps) {
        const int ebase = ch << 5;
        int e_l = ebase + lane;
        int s = 0, d = 0;
        if (e_l < E) { s = eidx[e_l]; d = eidx[(size_t)E + e_l]; }
        int batch = min(max(s >> 11, 0), Bm1);
        int off = batch << 11;
        int si = (s & NMASK) + off;
        int di = (d & NMASK) + off;
        const int cnt = min(32, E - ebase);
        for (int i = 0; i < cnt; i++) {
            int sii = __shfl_sync(FULL, si, i);
            int dii = __shfl_sync(FULL, di, i);
            float4 p1 = *(const float4*)&g_P[(size_t)sii * 256 + c];
            float4 p2 = *(const float4*)&g_P[(size_t)dii * 256 + 128 + c];
            float4 a  = *(const float4*)&ea[(size_t)(ebase + i) * 4];
            float h0 = p1.x + p2.x + b1v.x;
            float h1 = p1.y + p2.y + b1v.y;
            float h2 = p1.z + p2.z + b1v.z;
            float h3 = p1.w + p2.w + b1v.w;
            h0 = fmaf(a.x, w1a[0][0], fmaf(a.y, w1a[1][0], fmaf(a.z, w1a[2][0], fmaf(a.w, w1a[3][0], h0))));
            h1 = fmaf(a.x, w1a[0][1], fmaf(a.y, w1a[1][1], fmaf(a.z, w1a[2][1], fmaf(a.w, w1a[3][1], h1))));
            h2 = fmaf(a.x, w1a[0][2], fmaf(a.y, w1a[1][2], fmaf(a.z, w1a[2][2], fmaf(a.w, w1a[3][2], h2))));
            h3 = fmaf(a.x, w1a[0][3], fmaf(a.y, w1a[1][3], fmaf(a.z, w1a[2][3], fmaf(a.w, w1a[3][3], h3))));
            s0 += h0; q0 = fmaf(h0, h0, q0);
            s1 += h1; q1 = fmaf(h1, h1, q1);
            s2 += h2; q2 = fmaf(h2, h2, q2);
            s3 += h3; q3 = fmaf(h3, h3, q3);
        }
    }

    atomicAdd(&bsum[c + 0], s0); atomicAdd(&bsq[c + 0], q0);
    atomicAdd(&bsum[c + 1], s1); atomicAdd(&bsq[c + 1], q1);
    atomicAdd(&bsum[c + 2], s2); atomicAdd(&bsq[c + 2], q2);
    atomicAdd(&bsum[c + 3], s3); atomicAdd(&bsq[c + 3], q3);
    __syncthreads();
    if (tid < H) {
        atomicAdd(&g_sum[tid], bsum[tid]);
        atomicAdd(&g_sq[tid],  bsq[tid]);
    }
}

__global__ void finalize_stats_kernel(const float* __restrict__ gamma,
                                      const float* __restrict__ beta,
                                      float invE)
{
    int c = threadIdx.x;
    if (c < H) {
        float mu  = g_sum[c] * invE;
        float var = g_sq[c] * invE - mu * mu;
        float inv = rsqrtf(var + 1e-5f);
        float A = gamma[c] * inv;
        g_A[c] = A;
        g_B[c] = beta[c] - mu * A;
    }
}

// ---------------- pass B: gather + h recompute + BN affine + LeakyReLU + dot W2 ----------------
__global__ void __launch_bounds__(256) pass_b_kernel(
    const float* __restrict__ ea,
    const float* __restrict__ W1,
    const float* __restrict__ b1,
    const int* __restrict__ eidx,
    const float* __restrict__ W2,   // [128]
    const float* __restrict__ b2,   // [1]
    float* __restrict__ out,        // [E]
    int E, int Bm1)
{
    __shared__ float obuf[8][32];
    const int tid = threadIdx.x;
    const int lane = tid & 31;
    const int wrp = tid >> 5;

    const int c = lane * 4;
    float w1a[4][4];
#pragma unroll
    for (int k = 0; k < 4; k++) {
        float4 v = *(const float4*)&W1[(128 + k) * H + c];
        w1a[k][0] = v.x; w1a[k][1] = v.y; w1a[k][2] = v.z; w1a[k][3] = v.w;
    }
    const float4 b1v = *(const float4*)&b1[c];
    const float4 Av  = *(const float4*)&g_A[c];
    const float4 Bv  = *(const float4*)&g_B[c];
    const float4 w2v = *(const float4*)&W2[c];
    const float b2v  = b2[0];

    const int nwarps = gridDim.x * 8;
    const int gw = blockIdx.x * 8 + wrp;
    const int nchunks = (E + 31) >> 5;

    for (int ch = gw; ch < nchunks; ch += nwarps) {
        const int ebase = ch << 5;
        int e_l = ebase + lane;
        int s = 0, d = 0;
        if (e_l < E) { s = eidx[e_l]; d = eidx[(size_t)E + e_l]; }
        int batch = min(max(s >> 11, 0), Bm1);
        int off = batch << 11;
        int si = (s & NMASK) + off;
        int di = (d & NMASK) + off;
        const int cnt = min(32, E - ebase);
        for (int i = 0; i < cnt; i++) {
            int sii = __shfl_sync(FULL, si, i);
            int dii = __shfl_sync(FULL, di, i);
            float4 p1 = *(const float4*)&g_P[(size_t)sii * 256 + c];
            float4 p2 = *(const float4*)&g_P[(size_t)dii * 256 + 128 + c];
            float4 a  = *(const float4*)&ea[(size_t)(ebase + i) * 4];
            float h0 = p1.x + p2.x + b1v.x;
            float h1 = p1.y + p2.y + b1v.y;
            float h2 = p1.z + p2.z + b1v.z;
            float h3 = p1.w + p2.w + b1v.w;
            h0 = fmaf(a.x, w1a[0][0], fmaf(a.y, w1a[1][0], fmaf(a.z, w1a[2][0], fmaf(a.w, w1a[3][0], h0))));
            h1 = fmaf(a.x, w1a[0][1], fmaf(a.y, w1a[1][1], fmaf(a.z, w1a[2][1], fmaf(a.w, w1a[3][1], h1))));
            h2 = fmaf(a.x, w1a[0][2], fmaf(a.y, w1a[1][2], fmaf(a.z, w1a[2][2], fmaf(a.w, w1a[3][2], h2))));
            h3 = fmaf(a.x, w1a[0][3], fmaf(a.y, w1a[1][3], fmaf(a.z, w1a[2][3], fmaf(a.w, w1a[3][3], h3))));
            float t, r;
            t = fmaf(Av.x, h0, Bv.x); t = (t >= 0.f) ? t : 0.2f * t; r  = t * w2v.x;
            t = fmaf(Av.y, h1, Bv.y); t = (t >= 0.f) ? t : 0.2f * t; r  = fmaf(t, w2v.y, r);
            t = fmaf(Av.z, h2, Bv.z); t = (t >= 0.f) ? t : 0.2f * t; r  = fmaf(t, w2v.z, r);
            t = fmaf(Av.w, h3, Bv.w); t = (t >= 0.f) ? t : 0.2f * t; r  = fmaf(t, w2v.w, r);
#pragma unroll
            for (int o = 16; o > 0; o >>= 1)
                r += __shfl_xor_sync(FULL, r, o);
            if (lane == 0) obuf[wrp][i] = r + b2v;
        }
        __syncwarp();
        if (lane < cnt) out[ebase + lane] = obuf[wrp][lane];
        __syncwarp();
    }
}

extern "C" void kernel_launch(void* const* d_in, const int* in_sizes, int n_in,
                              void* d_out, int out_size)
{
    const float* z     = (const float*)d_in[0];
    const float* ea    = (const float*)d_in[1];
    const float* W1    = (const float*)d_in[2];
    const float* b1    = (const float*)d_in[3];
    const float* gamma = (const float*)d_in[4];
    const float* beta  = (const float*)d_in[5];
    const float* W2    = (const float*)d_in[6];
    const float* b2    = (const float*)d_in[7];
    const int*   eidx  = (const int*)d_in[8];     // int32 (JAX x64 disabled)

    const int E  = in_sizes[1] / 4;   // edge_attr is [E,4]
    const int BN = in_sizes[0] / 64;  // z is [B, N, 64]
    const int Bm1 = BN / 2048 - 1;
    float* out = (float*)d_out;

    cudaFuncSetAttribute(node_gemm_kernel,
                         cudaFuncAttributeMaxDynamicSharedMemorySize, NG_SMEM);

    init_stats_kernel<<<1, 128>>>();
    node_gemm_kernel<<<(BN + 63) / 64, 256, NG_SMEM>>>(z, W1, BN);
    pass_a_kernel<<<1184, 256>>>(ea, W1, b1, eidx, E, Bm1);
    finalize_stats_kernel<<<1, 128>>>(gamma, beta, 1.0f / (float)E);
    pass_b_kernel<<<1184, 256>>>(ea, W1, b1, eidx, W2, b2, out, E, Bm1);
}

// round 7
// speedup vs baseline: 7.2482x; 1.0833x over previous
#include <cuda_runtime.h>
#include <cuda_fp16.h>
#include <math.h>

#define H 128
#define NMASK 2047           // N = 2048
#define BN_MAX 65536
#define FULL 0xffffffffu

// P stored fp16: P[n][0:128] = zf[n] @ W1[0:64,:] ; P[n][128:256] = zf[n] @ W1[64:128,:]
__device__ __half g_P[(size_t)BN_MAX * 256];
__device__ float g_sum[H];
__device__ float g_sq[H];
__device__ float g_A[H];
__device__ float g_B[H];

__global__ void init_stats_kernel() {
    int t = threadIdx.x;
    if (t < H) { g_sum[t] = 0.f; g_sq[t] = 0.f; }
}

// ---------------- node GEMM: P[BN,256] = zf[BN,64] @ Wc[64,256], fp16 out ----------------
#define NG_SMEM ((64*256 + 64*64) * 4)
__global__ void __launch_bounds__(256) node_gemm_kernel(
    const float* __restrict__ zf,   // [BN, 64]
    const float* __restrict__ W1,   // [132, 128]
    int BN)
{
    extern __shared__ float smem[];
    float* Wc = smem;               // [64][256]
    float* xs = smem + 64 * 256;    // [64 nodes][64 k]

    const int tid = threadIdx.x;
    const int nb = blockIdx.x * 64;

    // Wc[k][c] = W1[k][c] (c<128) else W1[64+k][c-128]
    const float4* W1f4 = (const float4*)W1;   // row = 32 float4
#pragma unroll
    for (int it = 0; it < 16; it++) {
        int i = tid + it * 256;                // float4 index into Wc
        int k = i >> 6, c4 = i & 63;
        ((float4*)Wc)[i] = (c4 < 32) ? W1f4[k * 32 + c4]
                                     : W1f4[(64 + k) * 32 + (c4 - 32)];
    }
#pragma unroll
    for (int it = 0; it < 4; it++) {
        int i = tid + it * 256;                // float4 index
        int node = i >> 4, k4 = i & 15;
        int nn = min(nb + node, BN - 1);
        ((float4*)xs)[node * 16 + k4] = *(const float4*)&zf[(size_t)nn * 64 + k4 * 4];
    }
    __syncthreads();

    const int cg = tid & 31;       // col group: c0 = cg*4, c1 = 128+cg*4
    const int ng = tid >> 5;       // node group: nodes ng*8 .. ng*8+7
    const int c0 = cg * 4;
    const int c1 = 128 + cg * 4;

    float acc[8][8];
#pragma unroll
    for (int i = 0; i < 8; i++)
#pragma unroll
        for (int j = 0; j < 8; j++) acc[i][j] = 0.f;

#pragma unroll 4
    for (int k = 0; k < 64; k++) {
        float xk[8];
#pragma unroll
        for (int i = 0; i < 8; i++) xk[i] = xs[(ng * 8 + i) * 64 + k];
        const float4 w0 = *(const float4*)&Wc[k * 256 + c0];
        const float4 w1 = *(const float4*)&Wc[k * 256 + c1];
        const float wr[8] = {w0.x, w0.y, w0.z, w0.w, w1.x, w1.y, w1.z, w1.w};
#pragma unroll
        for (int i = 0; i < 8; i++)
#pragma unroll
            for (int j = 0; j < 8; j++)
                acc[i][j] = fmaf(xk[i], wr[j], acc[i][j]);
    }

#pragma unroll
    for (int i = 0; i < 8; i++) {
        int node = nb + ng * 8 + i;
        if (node < BN) {
            __half2 p0 = __floats2half2_rn(acc[i][0], acc[i][1]);
            __half2 p1 = __floats2half2_rn(acc[i][2], acc[i][3]);
            __half2 p2 = __floats2half2_rn(acc[i][4], acc[i][5]);
            __half2 p3 = __floats2half2_rn(acc[i][6], acc[i][7]);
            *(__half2*)&g_P[(size_t)node * 256 + c0]     = p0;
            *(__half2*)&g_P[(size_t)node * 256 + c0 + 2] = p1;
            *(__half2*)&g_P[(size_t)node * 256 + c1]     = p2;
            *(__half2*)&g_P[(size_t)node * 256 + c1 + 2] = p3;
        }
    }
}

__device__ __forceinline__ void load_p4(const __half* p, float& f0, float& f1, float& f2, float& f3) {
    uint2 u = *(const uint2*)p;
    __half2 a = *(__half2*)&u.x;
    __half2 b = *(__half2*)&u.y;
    float2 fa = __half22float2(a);
    float2 fb = __half22float2(b);
    f0 = fa.x; f1 = fa.y; f2 = fb.x; f3 = fb.y;
}

// ---------------- pass A: gather + h recompute + BN stats ----------------
__global__ void __launch_bounds__(256) pass_a_kernel(
    const float* __restrict__ ea,   // [E,4]
    const float* __restrict__ W1,   // [132,128]
    const float* __restrict__ b1,
    const int* __restrict__ eidx,   // [2,E] int32
    int E, int Bm1)
{
    __shared__ float bsum[H], bsq[H];
    const int tid = threadIdx.x;
    const int lane = tid & 31;
    const int wrp = tid >> 5;
    if (tid < H) { bsum[tid] = 0.f; bsq[tid] = 0.f; }
    __syncthreads();

    const int c = lane * 4;
    float w1a[4][4];
#pragma unroll
    for (int k = 0; k < 4; k++) {
        float4 v = *(const float4*)&W1[(128 + k) * H + c];
        w1a[k][0] = v.x; w1a[k][1] = v.y; w1a[k][2] = v.z; w1a[k][3] = v.w;
    }
    const float4 b1v = *(const float4*)&b1[c];

    float s0 = 0.f, s1 = 0.f, s2 = 0.f, s3 = 0.f;
    float q0 = 0.f, q1 = 0.f, q2 = 0.f, q3 = 0.f;

    const int nwarps = gridDim.x * 8;
    const int gw = blockIdx.x * 8 + wrp;
    const int nchunks = (E + 31) >> 5;

    for (int ch = gw; ch < nchunks; ch += nwarps) {
        const int ebase = ch << 5;
        int e_l = ebase + lane;
        int s = 0, d = 0;
        if (e_l < E) { s = eidx[e_l]; d = eidx[(size_t)E + e_l]; }
        int batch = min(max(s >> 11, 0), Bm1);
        int off = batch << 11;
        int si = (s & NMASK) + off;
        int di = (d & NMASK) + off;
        const int cnt = min(32, E - ebase);
        for (int i = 0; i < cnt; i++) {
            int sii = __shfl_sync(FULL, si, i);
            int dii = __shfl_sync(FULL, di, i);
            float p10, p11, p12, p13, p20, p21, p22, p23;
            load_p4(&g_P[(size_t)sii * 256 + c], p10, p11, p12, p13);
            load_p4(&g_P[(size_t)dii * 256 + 128 + c], p20, p21, p22, p23);
            float4 a = *(const float4*)&ea[(size_t)(ebase + i) * 4];
            float h0 = p10 + p20 + b1v.x;
            float h1 = p11 + p21 + b1v.y;
            float h2 = p12 + p22 + b1v.z;
            float h3 = p13 + p23 + b1v.w;
            h0 = fmaf(a.x, w1a[0][0], fmaf(a.y, w1a[1][0], fmaf(a.z, w1a[2][0], fmaf(a.w, w1a[3][0], h0))));
            h1 = fmaf(a.x, w1a[0][1], fmaf(a.y, w1a[1][1], fmaf(a.z, w1a[2][1], fmaf(a.w, w1a[3][1], h1))));
            h2 = fmaf(a.x, w1a[0][2], fmaf(a.y, w1a[1][2], fmaf(a.z, w1a[2][2], fmaf(a.w, w1a[3][2], h2))));
            h3 = fmaf(a.x, w1a[0][3], fmaf(a.y, w1a[1][3], fmaf(a.z, w1a[2][3], fmaf(a.w, w1a[3][3], h3))));
            s0 += h0; q0 = fmaf(h0, h0, q0);
            s1 += h1; q1 = fmaf(h1, h1, q1);
            s2 += h2; q2 = fmaf(h2, h2, q2);
            s3 += h3; q3 = fmaf(h3, h3, q3);
        }
    }

    atomicAdd(&bsum[c + 0], s0); atomicAdd(&bsq[c + 0], q0);
    atomicAdd(&bsum[c + 1], s1); atomicAdd(&bsq[c + 1], q1);
    atomicAdd(&bsum[c + 2], s2); atomicAdd(&bsq[c + 2], q2);
    atomicAdd(&bsum[c + 3], s3); atomicAdd(&bsq[c + 3], q3);
    __syncthreads();
    if (tid < H) {
        atomicAdd(&g_sum[tid], bsum[tid]);
        atomicAdd(&g_sq[tid],  bsq[tid]);
    }
}

__global__ void finalize_stats_kernel(const float* __restrict__ gamma,
                                      const float* __restrict__ beta,
                                      float invE)
{
    int c = threadIdx.x;
    if (c < H) {
        float mu  = g_sum[c] * invE;
        float var = g_sq[c] * invE - mu * mu;
        float inv = rsqrtf(var + 1e-5f);
        float A = gamma[c] * inv;
        g_A[c] = A;
        g_B[c] = beta[c] - mu * A;
    }
}

// ---------------- pass B: gather + BN affine + LeakyReLU + dot W2 ----------------
__global__ void __launch_bounds__(256) pass_b_kernel(
    const float* __restrict__ ea,
    const float* __restrict__ W1,
    const float* __restrict__ b1,
    const int* __restrict__ eidx,
    const float* __restrict__ W2,   // [128]
    const float* __restrict__ b2,   // [1]
    float* __restrict__ out,        // [E]
    int E, int Bm1)
{
    __shared__ float obuf[8][32];
    const int tid = threadIdx.x;
    const int lane = tid & 31;
    const int wrp = tid >> 5;

    const int c = lane * 4;
    float w1a[4][4];
#pragma unroll
    for (int k = 0; k < 4; k++) {
        float4 v = *(const float4*)&W1[(128 + k) * H + c];
        w1a[k][0] = v.x; w1a[k][1] = v.y; w1a[k][2] = v.z; w1a[k][3] = v.w;
    }
    const float4 b1v = *(const float4*)&b1[c];
    const float4 Av  = *(const float4*)&g_A[c];
    const float4 Bv  = *(const float4*)&g_B[c];
    const float4 w2v = *(const float4*)&W2[c];
    const float b2v  = b2[0];

    const int nwarps = gridDim.x * 8;
    const int gw = blockIdx.x * 8 + wrp;
    const int nchunks = (E + 31) >> 5;

    for (int ch = gw; ch < nchunks; ch += nwarps) {
        const int ebase = ch << 5;
        int e_l = ebase + lane;
        int s = 0, d = 0;
        if (e_l < E) { s = eidx[e_l]; d = eidx[(size_t)E + e_l]; }
        int batch = min(max(s >> 11, 0), Bm1);
        int off = batch << 11;
        int si = (s & NMASK) + off;
        int di = (d & NMASK) + off;
        const int cnt = min(32, E - ebase);
        for (int i = 0; i < cnt; i++) {
            int sii = __shfl_sync(FULL, si, i);
            int dii = __shfl_sync(FULL, di, i);
            float p10, p11, p12, p13, p20, p21, p22, p23;
            load_p4(&g_P[(size_t)sii * 256 + c], p10, p11, p12, p13);
            load_p4(&g_P[(size_t)dii * 256 + 128 + c], p20, p21, p22, p23);
            float4 a = *(const float4*)&ea[(size_t)(ebase + i) * 4];
            float h0 = p10 + p20 + b1v.x;
            float h1 = p11 + p21 + b1v.y;
            float h2 = p12 + p22 + b1v.z;
            float h3 = p13 + p23 + b1v.w;
            h0 = fmaf(a.x, w1a[0][0], fmaf(a.y, w1a[1][0], fmaf(a.z, w1a[2][0], fmaf(a.w, w1a[3][0], h0))));
            h1 = fmaf(a.x, w1a[0][1], fmaf(a.y, w1a[1][1], fmaf(a.z, w1a[2][1], fmaf(a.w, w1a[3][1], h1))));
            h2 = fmaf(a.x, w1a[0][2], fmaf(a.y, w1a[1][2], fmaf(a.z, w1a[2][2], fmaf(a.w, w1a[3][2], h2))));
            h3 = fmaf(a.x, w1a[0][3], fmaf(a.y, w1a[1][3], fmaf(a.z, w1a[2][3], fmaf(a.w, w1a[3][3], h3))));
            float t, r;
            t = fmaf(Av.x, h0, Bv.x); t = (t >= 0.f) ? t : 0.2f * t; r  = t * w2v.x;
            t = fmaf(Av.y, h1, Bv.y); t = (t >= 0.f) ? t : 0.2f * t; r  = fmaf(t, w2v.y, r);
            t = fmaf(Av.z, h2, Bv.z); t = (t >= 0.f) ? t : 0.2f * t; r  = fmaf(t, w2v.z, r);
            t = fmaf(Av.w, h3, Bv.w); t = (t >= 0.f) ? t : 0.2f * t; r  = fmaf(t, w2v.w, r);
#pragma unroll
            for (int o = 16; o > 0; o >>= 1)
                r += __shfl_xor_sync(FULL, r, o);
            if (lane == 0) obuf[wrp][i] = r + b2v;
        }
        __syncwarp();
        if (lane < cnt) out[ebase + lane] = obuf[wrp][lane];
        __syncwarp();
    }
}

extern "C" void kernel_launch(void* const* d_in, const int* in_sizes, int n_in,
                              void* d_out, int out_size)
{
    const float* z     = (const float*)d_in[0];
    const float* ea    = (const float*)d_in[1];
    const float* W1    = (const float*)d_in[2];
    const float* b1    = (const float*)d_in[3];
    const float* gamma = (const float*)d_in[4];
    const float* beta  = (const float*)d_in[5];
    const float* W2    = (const float*)d_in[6];
    const float* b2    = (const float*)d_in[7];
    const int*   eidx  = (const int*)d_in[8];     // int32 (JAX x64 disabled)

    const int E  = in_sizes[1] / 4;   // edge_attr is [E,4]
    const int BN = in_sizes[0] / 64;  // z is [B, N, 64]
    const int Bm1 = BN / 2048 - 1;
    float* out = (float*)d_out;

    cudaFuncSetAttribute(node_gemm_kernel,
                         cudaFuncAttributeMaxDynamicSharedMemorySize, NG_SMEM);

    init_stats_kernel<<<1, 128>>>();
    node_gemm_kernel<<<(BN + 63) / 64, 256, NG_SMEM>>>(z, W1, BN);
    pass_a_kernel<<<1184, 256>>>(ea, W1, b1, eidx, E, Bm1);
    finalize_stats_kernel<<<1, 128>>>(gamma, beta, 1.0f / (float)E);
    pass_b_kernel<<<1184, 256>>>(ea, W1, b1, eidx, W2, b2, out, E, Bm1);
}

// round 8
// speedup vs baseline: 8.2125x; 1.1330x over previous
#include <cuda_runtime.h>
#include <cuda_fp16.h>
#include <math.h>

#define H 128
#define NMASK 2047           // N = 2048
#define BN_MAX 65536
#define FULL 0xffffffffu

// P stored fp16: P[n][0:128] = zf[n] @ W1[0:64,:] ; P[n][128:256] = zf[n] @ W1[64:128,:]
__device__ __half g_P[(size_t)BN_MAX * 256];
__device__ float g_sum[H];
__device__ float g_sq[H];
__device__ float g_A[H];
__device__ float g_B[H];

__global__ void init_stats_kernel() {
    int t = threadIdx.x;
    if (t < H) { g_sum[t] = 0.f; g_sq[t] = 0.f; }
}

// ---------------- node GEMM: P[BN,256] = zf[BN,64] @ Wc[64,256], fp16 out ----------------
#define NG_SMEM ((64*256 + 64*64) * 4)
__global__ void __launch_bounds__(256) node_gemm_kernel(
    const float* __restrict__ zf,   // [BN, 64]
    const float* __restrict__ W1,   // [132, 128]
    int BN)
{
    extern __shared__ float smem[];
    float* Wc = smem;               // [64][256]
    float* xs = smem + 64 * 256;    // [64 nodes][64 k]

    const int tid = threadIdx.x;
    const int nb = blockIdx.x * 64;

    const float4* W1f4 = (const float4*)W1;   // row = 32 float4
#pragma unroll
    for (int it = 0; it < 16; it++) {
        int i = tid + it * 256;
        int k = i >> 6, c4 = i & 63;
        ((float4*)Wc)[i] = (c4 < 32) ? W1f4[k * 32 + c4]
                                     : W1f4[(64 + k) * 32 + (c4 - 32)];
    }
#pragma unroll
    for (int it = 0; it < 4; it++) {
        int i = tid + it * 256;
        int node = i >> 4, k4 = i & 15;
        int nn = min(nb + node, BN - 1);
        ((float4*)xs)[node * 16 + k4] = *(const float4*)&zf[(size_t)nn * 64 + k4 * 4];
    }
    __syncthreads();

    const int cg = tid & 31;
    const int ng = tid >> 5;
    const int c0 = cg * 4;
    const int c1 = 128 + cg * 4;

    float acc[8][8];
#pragma unroll
    for (int i = 0; i < 8; i++)
#pragma unroll
        for (int j = 0; j < 8; j++) acc[i][j] = 0.f;

#pragma unroll 4
    for (int k = 0; k < 64; k++) {
        float xk[8];
#pragma unroll
        for (int i = 0; i < 8; i++) xk[i] = xs[(ng * 8 + i) * 64 + k];
        const float4 w0 = *(const float4*)&Wc[k * 256 + c0];
        const float4 w1 = *(const float4*)&Wc[k * 256 + c1];
        const float wr[8] = {w0.x, w0.y, w0.z, w0.w, w1.x, w1.y, w1.z, w1.w};
#pragma unroll
        for (int i = 0; i < 8; i++)
#pragma unroll
            for (int j = 0; j < 8; j++)
                acc[i][j] = fmaf(xk[i], wr[j], acc[i][j]);
    }

#pragma unroll
    for (int i = 0; i < 8; i++) {
        int node = nb + ng * 8 + i;
        if (node < BN) {
            __half2 p0 = __floats2half2_rn(acc[i][0], acc[i][1]);
            __half2 p1 = __floats2half2_rn(acc[i][2], acc[i][3]);
            __half2 p2 = __floats2half2_rn(acc[i][4], acc[i][5]);
            __half2 p3 = __floats2half2_rn(acc[i][6], acc[i][7]);
            *(__half2*)&g_P[(size_t)node * 256 + c0]     = p0;
            *(__half2*)&g_P[(size_t)node * 256 + c0 + 2] = p1;
            *(__half2*)&g_P[(size_t)node * 256 + c1]     = p2;
            *(__half2*)&g_P[(size_t)node * 256 + c1 + 2] = p3;
        }
    }
}

__device__ __forceinline__ void cvt_p4(uint2 u, float& f0, float& f1, float& f2, float& f3) {
    __half2 a = *(__half2*)&u.x;
    __half2 b = *(__half2*)&u.y;
    float2 fa = __half22float2(a);
    float2 fb = __half22float2(b);
    f0 = fa.x; f1 = fa.y; f2 = fb.x; f3 = fb.y;
}

// ---------------- pass A: gather + h' recompute (no b1) + BN stats ----------------
__global__ void __launch_bounds__(256) pass_a_kernel(
    const float* __restrict__ ea,   // [E,4]
    const float* __restrict__ W1,   // [132,128]
    const int* __restrict__ eidx,   // [2,E] int32
    int E, int Bm1)
{
    __shared__ float bsum[H], bsq[H];
    const int tid = threadIdx.x;
    const int lane = tid & 31;
    const int wrp = tid >> 5;
    if (tid < H) { bsum[tid] = 0.f; bsq[tid] = 0.f; }
    __syncthreads();

    const int c = lane * 4;
    float w1a[4][4];
#pragma unroll
    for (int k = 0; k < 4; k++) {
        float4 v = *(const float4*)&W1[(128 + k) * H + c];
        w1a[k][0] = v.x; w1a[k][1] = v.y; w1a[k][2] = v.z; w1a[k][3] = v.w;
    }

    float s0 = 0.f, s1 = 0.f, s2 = 0.f, s3 = 0.f;
    float q0 = 0.f, q1 = 0.f, q2 = 0.f, q3 = 0.f;

    const int nwarps = gridDim.x * 8;
    const int gw = blockIdx.x * 8 + wrp;
    const int nchunks = (E + 31) >> 5;

    for (int ch = gw; ch < nchunks; ch += nwarps) {
        const int ebase = ch << 5;
        int e_l = ebase + lane;
        int s = 0, d = 0;
        if (e_l < E) { s = eidx[e_l]; d = eidx[(size_t)E + e_l]; }
        int batch = min(max(s >> 11, 0), Bm1);
        int off = batch << 11;
        int si = (s & NMASK) + off;
        int di = (d & NMASK) + off;

        if (ebase + 32 <= E) {
            // full chunk: batched loads, compile-time trip counts
#pragma unroll 1
            for (int i0 = 0; i0 < 32; i0 += 4) {
                uint2 u1[4], u2[4]; float4 av[4];
#pragma unroll
                for (int j = 0; j < 4; j++) {
                    int sii = __shfl_sync(FULL, si, i0 + j);
                    int dii = __shfl_sync(FULL, di, i0 + j);
                    u1[j] = *(const uint2*)&g_P[(size_t)sii * 256 + c];
                    u2[j] = *(const uint2*)&g_P[(size_t)dii * 256 + 128 + c];
                    av[j] = *(const float4*)&ea[(size_t)(ebase + i0 + j) * 4];
                }
#pragma unroll
                for (int j = 0; j < 4; j++) {
                    float p10, p11, p12, p13, p20, p21, p22, p23;
                    cvt_p4(u1[j], p10, p11, p12, p13);
                    cvt_p4(u2[j], p20, p21, p22, p23);
                    float4 a = av[j];
                    float h0 = p10 + p20;
                    float h1 = p11 + p21;
                    float h2 = p12 + p22;
                    float h3 = p13 + p23;
                    h0 = fmaf(a.x, w1a[0][0], fmaf(a.y, w1a[1][0], fmaf(a.z, w1a[2][0], fmaf(a.w, w1a[3][0], h0))));
                    h1 = fmaf(a.x, w1a[0][1], fmaf(a.y, w1a[1][1], fmaf(a.z, w1a[2][1], fmaf(a.w, w1a[3][1], h1))));
                    h2 = fmaf(a.x, w1a[0][2], fmaf(a.y, w1a[1][2], fmaf(a.z, w1a[2][2], fmaf(a.w, w1a[3][2], h2))));
                    h3 = fmaf(a.x, w1a[0][3], fmaf(a.y, w1a[1][3], fmaf(a.z, w1a[2][3], fmaf(a.w, w1a[3][3], h3))));
                    s0 += h0; q0 = fmaf(h0, h0, q0);
                    s1 += h1; q1 = fmaf(h1, h1, q1);
                    s2 += h2; q2 = fmaf(h2, h2, q2);
                    s3 += h3; q3 = fmaf(h3, h3, q3);
                }
            }
        } else {
            const int cnt = E - ebase;
            for (int i = 0; i < cnt; i++) {
                int sii = __shfl_sync(FULL, si, i);
                int dii = __shfl_sync(FULL, di, i);
                uint2 u1 = *(const uint2*)&g_P[(size_t)sii * 256 + c];
                uint2 u2 = *(const uint2*)&g_P[(size_t)dii * 256 + 128 + c];
                float p10, p11, p12, p13, p20, p21, p22, p23;
                cvt_p4(u1, p10, p11, p12, p13);
                cvt_p4(u2, p20, p21, p22, p23);
                float4 a = *(const float4*)&ea[(size_t)(ebase + i) * 4];
                float h0 = p10 + p20;
                float h1 = p11 + p21;
                float h2 = p12 + p22;
                float h3 = p13 + p23;
                h0 = fmaf(a.x, w1a[0][0], fmaf(a.y, w1a[1][0], fmaf(a.z, w1a[2][0], fmaf(a.w, w1a[3][0], h0))));
                h1 = fmaf(a.x, w1a[0][1], fmaf(a.y, w1a[1][1], fmaf(a.z, w1a[2][1], fmaf(a.w, w1a[3][1], h1))));
                h2 = fmaf(a.x, w1a[0][2], fmaf(a.y, w1a[1][2], fmaf(a.z, w1a[2][2], fmaf(a.w, w1a[3][2], h2))));
                h3 = fmaf(a.x, w1a[0][3], fmaf(a.y, w1a[1][3], fmaf(a.z, w1a[2][3], fmaf(a.w, w1a[3][3], h3))));
                s0 += h0; q0 = fmaf(h0, h0, q0);
                s1 += h1; q1 = fmaf(h1, h1, q1);
                s2 += h2; q2 = fmaf(h2, h2, q2);
                s3 += h3; q3 = fmaf(h3, h3, q3);
            }
        }
    }

    atomicAdd(&bsum[c + 0], s0); atomicAdd(&bsq[c + 0], q0);
    atomicAdd(&bsum[c + 1], s1); atomicAdd(&bsq[c + 1], q1);
    atomicAdd(&bsum[c + 2], s2); atomicAdd(&bsq[c + 2], q2);
    atomicAdd(&bsum[c + 3], s3); atomicAdd(&bsq[c + 3], q3);
    __syncthreads();
    if (tid < H) {
        atomicAdd(&g_sum[tid], bsum[tid]);
        atomicAdd(&g_sq[tid],  bsq[tid]);
    }
}

// stats are over h' = h - b1. var(h)=var(h'), mu = mu'+b1.
// A = gamma*rsqrt(var+eps);  B_fold = beta - mu'*A  (b1 absorbed; pass_b uses h')
__global__ void finalize_stats_kernel(const float* __restrict__ gamma,
                                      const float* __restrict__ beta,
                                      float invE)
{
    int c = threadIdx.x;
    if (c < H) {
        float mup = g_sum[c] * invE;
        float var = g_sq[c] * invE - mup * mup;
        float inv = rsqrtf(var + 1e-5f);
        float A = gamma[c] * inv;
        g_A[c] = A;
        g_B[c] = beta[c] - mup * A;
    }
}

// ---------------- pass B: gather + BN affine (b1 folded) + LeakyReLU + dot W2 ----------------
__global__ void __launch_bounds__(256) pass_b_kernel(
    const float* __restrict__ ea,
    const float* __restrict__ W1,
    const int* __restrict__ eidx,
    const float* __restrict__ W2,   // [128]
    const float* __restrict__ b2,   // [1]
    float* __restrict__ out,        // [E]
    int E, int Bm1)
{
    __shared__ float obuf[8][32];
    const int tid = threadIdx.x;
    const int lane = tid & 31;
    const int wrp = tid >> 5;

    const int c = lane * 4;
    float w1a[4][4];
#pragma unroll
    for (int k = 0; k < 4; k++) {
        float4 v = *(const float4*)&W1[(128 + k) * H + c];
        w1a[k][0] = v.x; w1a[k][1] = v.y; w1a[k][2] = v.z; w1a[k][3] = v.w;
    }
    const float4 Av  = *(const float4*)&g_A[c];
    const float4 Bv  = *(const float4*)&g_B[c];
    const float4 w2v = *(const float4*)&W2[c];
    const float b2v  = b2[0];

    const int nwarps = gridDim.x * 8;
    const int gw = blockIdx.x * 8 + wrp;
    const int nchunks = (E + 31) >> 5;

    for (int ch = gw; ch < nchunks; ch += nwarps) {
        const int ebase = ch << 5;
        int e_l = ebase + lane;
        int s = 0, d = 0;
        if (e_l < E) { s = eidx[e_l]; d = eidx[(size_t)E + e_l]; }
        int batch = min(max(s >> 11, 0), Bm1);
        int off = batch << 11;
        int si = (s & NMASK) + off;
        int di = (d & NMASK) + off;

        if (ebase + 32 <= E) {
#pragma unroll 1
            for (int i0 = 0; i0 < 32; i0 += 4) {
                uint2 u1[4], u2[4]; float4 av[4];
#pragma unroll
                for (int j = 0; j < 4; j++) {
                    int sii = __shfl_sync(FULL, si, i0 + j);
                    int dii = __shfl_sync(FULL, di, i0 + j);
                    u1[j] = *(const uint2*)&g_P[(size_t)sii * 256 + c];
                    u2[j] = *(const uint2*)&g_P[(size_t)dii * 256 + 128 + c];
                    av[j] = *(const float4*)&ea[(size_t)(ebase + i0 + j) * 4];
                }
#pragma unroll
                for (int j = 0; j < 4; j++) {
                    float p10, p11, p12, p13, p20, p21, p22, p23;
                    cvt_p4(u1[j], p10, p11, p12, p13);
                    cvt_p4(u2[j], p20, p21, p22, p23);
                    float4 a = av[j];
                    float h0 = p10 + p20;
                    float h1 = p11 + p21;
                    float h2 = p12 + p22;
                    float h3 = p13 + p23;
                    h0 = fmaf(a.x, w1a[0][0], fmaf(a.y, w1a[1][0], fmaf(a.z, w1a[2][0], fmaf(a.w, w1a[3][0], h0))));
                    h1 = fmaf(a.x, w1a[0][1], fmaf(a.y, w1a[1][1], fmaf(a.z, w1a[2][1], fmaf(a.w, w1a[3][1], h1))));
                    h2 = fmaf(a.x, w1a[0][2], fmaf(a.y, w1a[1][2], fmaf(a.z, w1a[2][2], fmaf(a.w, w1a[3][2], h2))));
                    h3 = fmaf(a.x, w1a[0][3], fmaf(a.y, w1a[1][3], fmaf(a.z, w1a[2][3], fmaf(a.w, w1a[3][3], h3))));
                    float t, r;
                    t = fmaf(Av.x, h0, Bv.x); t = (t >= 0.f) ? t : 0.2f * t; r  = t * w2v.x;
                    t = fmaf(Av.y, h1, Bv.y); t = (t >= 0.f) ? t : 0.2f * t; r  = fmaf(t, w2v.y, r);
                    t = fmaf(Av.z, h2, Bv.z); t = (t >= 0.f) ? t : 0.2f * t; r  = fmaf(t, w2v.z, r);
                    t = fmaf(Av.w, h3, Bv.w); t = (t >= 0.f) ? t : 0.2f * t; r  = fmaf(t, w2v.w, r);
#pragma unroll
                    for (int o = 16; o > 0; o >>= 1)
                        r += __shfl_xor_sync(FULL, r, o);
                    if (lane == 0) obuf[wrp][i0 + j] = r + b2v;
                }
            }
            __syncwarp();
            out[ebase + lane] = obuf[wrp][lane];
            __syncwarp();
        } else {
            const int cnt = E - ebase;
            for (int i = 0; i < cnt; i++) {
                int sii = __shfl_sync(FULL, si, i);
                int dii = __shfl_sync(FULL, di, i);
                uint2 u1 = *(const uint2*)&g_P[(size_t)sii * 256 + c];
                uint2 u2 = *(const uint2*)&g_P[(size_t)dii * 256 + 128 + c];
                float p10, p11, p12, p13, p20, p21, p22, p23;
                cvt_p4(u1, p10, p11, p12, p13);
                cvt_p4(u2, p20, p21, p22, p23);
                float4 a = *(const float4*)&ea[(size_t)(ebase + i) * 4];
                float h0 = p10 + p20;
                float h1 = p11 + p21;
                float h2 = p12 + p22;
                float h3 = p13 + p23;
                h0 = fmaf(a.x, w1a[0][0], fmaf(a.y, w1a[1][0], fmaf(a.z, w1a[2][0], fmaf(a.w, w1a[3][0], h0))));
                h1 = fmaf(a.x, w1a[0][1], fmaf(a.y, w1a[1][1], fmaf(a.z, w1a[2][1], fmaf(a.w, w1a[3][1], h1))));
                h2 = fmaf(a.x, w1a[0][2], fmaf(a.y, w1a[1][2], fmaf(a.z, w1a[2][2], fmaf(a.w, w1a[3][2], h2))));
                h3 = fmaf(a.x, w1a[0][3], fmaf(a.y, w1a[1][3], fmaf(a.z, w1a[2][3], fmaf(a.w, w1a[3][3], h3))));
                float t, r;
                t = fmaf(Av.x, h0, Bv.x); t = (t >= 0.f) ? t : 0.2f * t; r  = t * w2v.x;
                t = fmaf(Av.y, h1, Bv.y); t = (t >= 0.f) ? t : 0.2f * t; r  = fmaf(t, w2v.y, r);
                t = fmaf(Av.z, h2, Bv.z); t = (t >= 0.f) ? t : 0.2f * t; r  = fmaf(t, w2v.z, r);
                t = fmaf(Av.w, h3, Bv.w); t = (t >= 0.f) ? t : 0.2f * t; r  = fmaf(t, w2v.w, r);
#pragma unroll
                for (int o = 16; o > 0; o >>= 1)
                    r += __shfl_xor_sync(FULL, r, o);
                if (lane == 0) obuf[wrp][i] = r + b2v;
            }
            __syncwarp();
            if (lane < cnt) out[ebase + lane] = obuf[wrp][lane];
            __syncwarp();
        }
    }
}

extern "C" void kernel_launch(void* const* d_in, const int* in_sizes, int n_in,
                              void* d_out, int out_size)
{
    const float* z     = (const float*)d_in[0];
    const float* ea    = (const float*)d_in[1];
    const float* W1    = (const float*)d_in[2];
    const float* gamma = (const float*)d_in[4];
    const float* beta  = (const float*)d_in[5];
    const float* W2    = (const float*)d_in[6];
    const float* b2    = (const float*)d_in[7];
    const int*   eidx  = (const int*)d_in[8];     // int32 (JAX x64 disabled)

    const int E  = in_sizes[1] / 4;   // edge_attr is [E,4]
    const int BN = in_sizes[0] / 64;  // z is [B, N, 64]
    const int Bm1 = BN / 2048 - 1;
    float* out = (float*)d_out;

    cudaFuncSetAttribute(node_gemm_kernel,
                         cudaFuncAttributeMaxDynamicSharedMemorySize, NG_SMEM);

    init_stats_kernel<<<1, 128>>>();
    node_gemm_kernel<<<(BN + 63) / 64, 256, NG_SMEM>>>(z, W1, BN);
    pass_a_kernel<<<1184, 256>>>(ea, W1, eidx, E, Bm1);
    finalize_stats_kernel<<<1, 128>>>(gamma, beta, 1.0f / (float)E);
    pass_b_kernel<<<1184, 256>>>(ea, W1, eidx, W2, b2, out, E, Bm1);
}

// round 9
// speedup vs baseline: 8.7308x; 1.0631x over previous
#include <cuda_runtime.h>
#include <cuda_fp16.h>
#include <math.h>

#define H 128
#define NMASK 2047           // N = 2048
#define BN_MAX 65536
#define FULL 0xffffffffu

// P stored fp16: P[n][0:128] = zf[n] @ W1[0:64,:] ; P[n][128:256] = zf[n] @ W1[64:128,:]
__device__ __half g_P[(size_t)BN_MAX * 256];
__device__ float g_sum[H];
__device__ float g_sq[H];
__device__ float g_A[H];
__device__ float g_B[H];

__global__ void init_stats_kernel() {
    int t = threadIdx.x;
    if (t < H) { g_sum[t] = 0.f; g_sq[t] = 0.f; }
}

// ---------------- node GEMM: P[BN,256] = zf[BN,64] @ Wc[64,256], fp16 out ----------------
#define NG_SMEM ((64*256 + 64*64) * 4)
__global__ void __launch_bounds__(256) node_gemm_kernel(
    const float* __restrict__ zf,   // [BN, 64]
    const float* __restrict__ W1,   // [132, 128]
    int BN)
{
    extern __shared__ float smem[];
    float* Wc = smem;               // [64][256]
    float* xs = smem + 64 * 256;    // [64 nodes][64 k]

    const int tid = threadIdx.x;
    const int nb = blockIdx.x * 64;

    const float4* W1f4 = (const float4*)W1;   // row = 32 float4
#pragma unroll
    for (int it = 0; it < 16; it++) {
        int i = tid + it * 256;
        int k = i >> 6, c4 = i & 63;
        ((float4*)Wc)[i] = (c4 < 32) ? W1f4[k * 32 + c4]
                                     : W1f4[(64 + k) * 32 + (c4 - 32)];
    }
#pragma unroll
    for (int it = 0; it < 4; it++) {
        int i = tid + it * 256;
        int node = i >> 4, k4 = i & 15;
        int nn = min(nb + node, BN - 1);
        ((float4*)xs)[node * 16 + k4] = *(const float4*)&zf[(size_t)nn * 64 + k4 * 4];
    }
    __syncthreads();

    const int cg = tid & 31;
    const int ng = tid >> 5;
    const int c0 = cg * 4;
    const int c1 = 128 + cg * 4;

    float acc[8][8];
#pragma unroll
    for (int i = 0; i < 8; i++)
#pragma unroll
        for (int j = 0; j < 8; j++) acc[i][j] = 0.f;

#pragma unroll 4
    for (int k = 0; k < 64; k++) {
        float xk[8];
#pragma unroll
        for (int i = 0; i < 8; i++) xk[i] = xs[(ng * 8 + i) * 64 + k];
        const float4 w0 = *(const float4*)&Wc[k * 256 + c0];
        const float4 w1 = *(const float4*)&Wc[k * 256 + c1];
        const float wr[8] = {w0.x, w0.y, w0.z, w0.w, w1.x, w1.y, w1.z, w1.w};
#pragma unroll
        for (int i = 0; i < 8; i++)
#pragma unroll
            for (int j = 0; j < 8; j++)
                acc[i][j] = fmaf(xk[i], wr[j], acc[i][j]);
    }

#pragma unroll
    for (int i = 0; i < 8; i++) {
        int node = nb + ng * 8 + i;
        if (node < BN) {
            __half2 p0 = __floats2half2_rn(acc[i][0], acc[i][1]);
            __half2 p1 = __floats2half2_rn(acc[i][2], acc[i][3]);
            __half2 p2 = __floats2half2_rn(acc[i][4], acc[i][5]);
            __half2 p3 = __floats2half2_rn(acc[i][6], acc[i][7]);
            *(__half2*)&g_P[(size_t)node * 256 + c0]     = p0;
            *(__half2*)&g_P[(size_t)node * 256 + c0 + 2] = p1;
            *(__half2*)&g_P[(size_t)node * 256 + c1]     = p2;
            *(__half2*)&g_P[(size_t)node * 256 + c1 + 2] = p3;
        }
    }
}

// ---------------- pass A: 2 edges/warp, half2 math, BN stats over h' (no b1) ----------------
__global__ void __launch_bounds__(256, 2) pass_a_kernel(
    const float* __restrict__ ea,   // [E,4]
    const float* __restrict__ W1,   // [132,128]
    const int* __restrict__ eidx,   // [2,E] int32
    int E, int Bm1)
{
    __shared__ float bsum[H], bsq[H];
    const int tid  = threadIdx.x;
    const int lane = tid & 31;
    const int wrp  = tid >> 5;
    const int hf   = lane >> 4;      // which edge of the pair
    const int sub  = lane & 15;      // position within edge group
    const int ch   = sub * 8;        // 8 channels per lane
    if (tid < H) { bsum[tid] = 0.f; bsq[tid] = 0.f; }
    __syncthreads();

    // attr weights (rows 128..131, cols ch..ch+7) packed half2
    __half2 w1ah[4][4];
#pragma unroll
    for (int k = 0; k < 4; k++) {
        float4 v0 = *(const float4*)&W1[(128 + k) * H + ch];
        float4 v1 = *(const float4*)&W1[(128 + k) * H + ch + 4];
        w1ah[k][0] = __floats2half2_rn(v0.x, v0.y);
        w1ah[k][1] = __floats2half2_rn(v0.z, v0.w);
        w1ah[k][2] = __floats2half2_rn(v1.x, v1.y);
        w1ah[k][3] = __floats2half2_rn(v1.z, v1.w);
    }

    float sacc[8], qacc[8];
#pragma unroll
    for (int j = 0; j < 8; j++) { sacc[j] = 0.f; qacc[j] = 0.f; }
    const __half2 z2 = __float2half2_rn(0.f);

    const int nwarps = gridDim.x * 8;
    const int gw = blockIdx.x * 8 + wrp;
    const int nchunks = (E + 31) >> 5;

    for (int chk = gw; chk < nchunks; chk += nwarps) {
        const int ebase = chk << 5;
        int e_l = ebase + lane;
        int s = 0, d = 0;
        if (e_l < E) { s = eidx[e_l]; d = eidx[(size_t)E + e_l]; }
        int batch = min(max(s >> 11, 0), Bm1);
        int off = batch << 11;
        int si = (s & NMASK) + off;
        int di = (d & NMASK) + off;

        __half2 sum2[4] = {z2, z2, z2, z2};
        __half2 sq2[4]  = {z2, z2, z2, z2};

        if (ebase + 32 <= E) {
#pragma unroll 1
            for (int ii = 0; ii < 16; ii += 4) {
                uint4 u1[4], u2[4]; float4 av[4];
#pragma unroll
                for (int b = 0; b < 4; b++) {
                    int srcl = 2 * (ii + b) + hf;
                    int sii = __shfl_sync(FULL, si, srcl);
                    int dii = __shfl_sync(FULL, di, srcl);
                    u1[b] = *(const uint4*)&g_P[(size_t)sii * 256 + ch];
                    u2[b] = *(const uint4*)&g_P[(size_t)dii * 256 + 128 + ch];
                    av[b] = *(const float4*)&ea[(size_t)(ebase + srcl) * 4];
                }
#pragma unroll
                for (int b = 0; b < 4; b++) {
                    __half2 p1[4], p2[4];
                    p1[0] = *(__half2*)&u1[b].x; p1[1] = *(__half2*)&u1[b].y;
                    p1[2] = *(__half2*)&u1[b].z; p1[3] = *(__half2*)&u1[b].w;
                    p2[0] = *(__half2*)&u2[b].x; p2[1] = *(__half2*)&u2[b].y;
                    p2[2] = *(__half2*)&u2[b].z; p2[3] = *(__half2*)&u2[b].w;
                    __half2 a0 = __floats2half2_rn(av[b].x, av[b].x);
                    __half2 a1 = __floats2half2_rn(av[b].y, av[b].y);
                    __half2 a2 = __floats2half2_rn(av[b].z, av[b].z);
                    __half2 a3 = __floats2half2_rn(av[b].w, av[b].w);
#pragma unroll
                    for (int j = 0; j < 4; j++) {
                        __half2 hh = __hadd2(p1[j], p2[j]);
                        hh = __hfma2(a0, w1ah[0][j], hh);
                        hh = __hfma2(a1, w1ah[1][j], hh);
                        hh = __hfma2(a2, w1ah[2][j], hh);
                        hh = __hfma2(a3, w1ah[3][j], hh);
                        sum2[j] = __hadd2(sum2[j], hh);
                        sq2[j]  = __hfma2(hh, hh, sq2[j]);
                    }
                }
            }
        } else {
            const int cnt = E - ebase;
            for (int i2 = 0; i2 < cnt; i2 += 2) {
                int srcl = min(i2 + hf, cnt - 1);
                int sii = __shfl_sync(FULL, si, srcl);
                int dii = __shfl_sync(FULL, di, srcl);
                uint4 u1 = *(const uint4*)&g_P[(size_t)sii * 256 + ch];
                uint4 u2 = *(const uint4*)&g_P[(size_t)dii * 256 + 128 + ch];
                float4 a = *(const float4*)&ea[(size_t)(ebase + srcl) * 4];
                if (i2 + hf < cnt) {
                    __half2 p1[4], p2[4];
                    p1[0] = *(__half2*)&u1.x; p1[1] = *(__half2*)&u1.y;
                    p1[2] = *(__half2*)&u1.z; p1[3] = *(__half2*)&u1.w;
                    p2[0] = *(__half2*)&u2.x; p2[1] = *(__half2*)&u2.y;
                    p2[2] = *(__half2*)&u2.z; p2[3] = *(__half2*)&u2.w;
                    __half2 a0 = __floats2half2_rn(a.x, a.x);
                    __half2 a1 = __floats2half2_rn(a.y, a.y);
                    __half2 a2 = __floats2half2_rn(a.z, a.z);
                    __half2 a3 = __floats2half2_rn(a.w, a.w);
#pragma unroll
                    for (int j = 0; j < 4; j++) {
                        __half2 hh = __hadd2(p1[j], p2[j]);
                        hh = __hfma2(a0, w1ah[0][j], hh);
                        hh = __hfma2(a1, w1ah[1][j], hh);
                        hh = __hfma2(a2, w1ah[2][j], hh);
                        hh = __hfma2(a3, w1ah[3][j], hh);
                        sum2[j] = __hadd2(sum2[j], hh);
                        sq2[j]  = __hfma2(hh, hh, sq2[j]);
                    }
                }
            }
        }
        // flush chunk-local half accumulators to fp32
#pragma unroll
        for (int j = 0; j < 4; j++) {
            float2 fs = __half22float2(sum2[j]);
            float2 fq = __half22float2(sq2[j]);
            sacc[2*j]   += fs.x; sacc[2*j+1] += fs.y;
            qacc[2*j]   += fq.x; qacc[2*j+1] += fq.y;
        }
    }

#pragma unroll
    for (int j = 0; j < 8; j++) {
        atomicAdd(&bsum[ch + j], sacc[j]);
        atomicAdd(&bsq [ch + j], qacc[j]);
    }
    __syncthreads();
    if (tid < H) {
        atomicAdd(&g_sum[tid], bsum[tid]);
        atomicAdd(&g_sq[tid],  bsq[tid]);
    }
}

// stats over h' = h - b1: var(h)=var(h'), b1 absorbed into B_fold.
__global__ void finalize_stats_kernel(const float* __restrict__ gamma,
                                      const float* __restrict__ beta,
                                      float invE)
{
    int c = threadIdx.x;
    if (c < H) {
        float mup = g_sum[c] * invE;
        float var = g_sq[c] * invE - mup * mup;
        float inv = rsqrtf(var + 1e-5f);
        float A = gamma[c] * inv;
        g_A[c] = A;
        g_B[c] = beta[c] - mup * A;
    }
}

// ---------------- pass B: 2 edges/warp, fp32 tail, BN affine + LeakyReLU + dot W2 ----------------
__global__ void __launch_bounds__(256, 2) pass_b_kernel(
    const float* __restrict__ ea,
    const float* __restrict__ W1,
    const int* __restrict__ eidx,
    const float* __restrict__ W2,   // [128]
    const float* __restrict__ b2,   // [1]
    float* __restrict__ out,        // [E]
    int E, int Bm1)
{
    __shared__ float obuf[8][32];
    const int tid  = threadIdx.x;
    const int lane = tid & 31;
    const int wrp  = tid >> 5;
    const int hf   = lane >> 4;
    const int sub  = lane & 15;
    const int ch   = sub * 8;

    float w1a[4][8];
#pragma unroll
    for (int k = 0; k < 4; k++) {
        float4 v0 = *(const float4*)&W1[(128 + k) * H + ch];
        float4 v1 = *(const float4*)&W1[(128 + k) * H + ch + 4];
        w1a[k][0] = v0.x; w1a[k][1] = v0.y; w1a[k][2] = v0.z; w1a[k][3] = v0.w;
        w1a[k][4] = v1.x; w1a[k][5] = v1.y; w1a[k][6] = v1.z; w1a[k][7] = v1.w;
    }
    float Av[8], Bv[8], w2v[8];
    {
        float4 t0 = *(const float4*)&g_A[ch];  float4 t1 = *(const float4*)&g_A[ch+4];
        Av[0]=t0.x; Av[1]=t0.y; Av[2]=t0.z; Av[3]=t0.w; Av[4]=t1.x; Av[5]=t1.y; Av[6]=t1.z; Av[7]=t1.w;
        float4 u0 = *(const float4*)&g_B[ch];  float4 u1 = *(const float4*)&g_B[ch+4];
        Bv[0]=u0.x; Bv[1]=u0.y; Bv[2]=u0.z; Bv[3]=u0.w; Bv[4]=u1.x; Bv[5]=u1.y; Bv[6]=u1.z; Bv[7]=u1.w;
        float4 s0 = *(const float4*)&W2[ch];   float4 s1 = *(const float4*)&W2[ch+4];
        w2v[0]=s0.x; w2v[1]=s0.y; w2v[2]=s0.z; w2v[3]=s0.w; w2v[4]=s1.x; w2v[5]=s1.y; w2v[6]=s1.z; w2v[7]=s1.w;
    }
    const float b2v = b2[0];

    const int nwarps = gridDim.x * 8;
    const int gw = blockIdx.x * 8 + wrp;
    const int nchunks = (E + 31) >> 5;

    for (int chk = gw; chk < nchunks; chk += nwarps) {
        const int ebase = chk << 5;
        int e_l = ebase + lane;
        int s = 0, d = 0;
        if (e_l < E) { s = eidx[e_l]; d = eidx[(size_t)E + e_l]; }
        int batch = min(max(s >> 11, 0), Bm1);
        int off = batch << 11;
        int si = (s & NMASK) + off;
        int di = (d & NMASK) + off;

        if (ebase + 32 <= E) {
#pragma unroll 1
            for (int ii = 0; ii < 16; ii += 2) {
                uint4 u1[2], u2[2]; float4 av[2];
#pragma unroll
                for (int b = 0; b < 2; b++) {
                    int srcl = 2 * (ii + b) + hf;
                    int sii = __shfl_sync(FULL, si, srcl);
                    int dii = __shfl_sync(FULL, di, srcl);
                    u1[b] = *(const uint4*)&g_P[(size_t)sii * 256 + ch];
                    u2[b] = *(const uint4*)&g_P[(size_t)dii * 256 + 128 + ch];
                    av[b] = *(const float4*)&ea[(size_t)(ebase + srcl) * 4];
                }
#pragma unroll
                for (int b = 0; b < 2; b++) {
                    float h[8];
#pragma unroll
                    for (int j = 0; j < 4; j++) {
                        __half2 hh = __hadd2(((__half2*)&u1[b])[j], ((__half2*)&u2[b])[j]);
                        float2 f = __half22float2(hh);
                        h[2*j] = f.x; h[2*j+1] = f.y;
                    }
                    const float ax = av[b].x, ay = av[b].y, az = av[b].z, aw = av[b].w;
                    float r = 0.f;
#pragma unroll
                    for (int c8 = 0; c8 < 8; c8++) {
                        float hv = h[c8];
                        hv = fmaf(ax, w1a[0][c8], hv);
                        hv = fmaf(ay, w1a[1][c8], hv);
                        hv = fmaf(az, w1a[2][c8], hv);
                        hv = fmaf(aw, w1a[3][c8], hv);
                        float t = fmaf(Av[c8], hv, Bv[c8]);
                        t = (t >= 0.f) ? t : 0.2f * t;
                        r = fmaf(t, w2v[c8], r);
                    }
#pragma unroll
                    for (int o = 8; o > 0; o >>= 1)
                        r += __shfl_xor_sync(FULL, r, o);
                    if (sub == 0) obuf[wrp][2 * (ii + b) + hf] = r + b2v;
                }
            }
            __syncwarp();
            out[ebase + lane] = obuf[wrp][lane];
            __syncwarp();
        } else {
            const int cnt = E - ebase;
            for (int i2 = 0; i2 < cnt; i2 += 2) {
                int srcl = min(i2 + hf, cnt - 1);
                int sii = __shfl_sync(FULL, si, srcl);
                int dii = __shfl_sync(FULL, di, srcl);
                uint4 u1 = *(const uint4*)&g_P[(size_t)sii * 256 + ch];
                uint4 u2 = *(const uint4*)&g_P[(size_t)dii * 256 + 128 + ch];
                float4 a = *(const float4*)&ea[(size_t)(ebase + srcl) * 4];
                float h[8];
#pragma unroll
                for (int j = 0; j < 4; j++) {
                    __half2 hh = __hadd2(((__half2*)&u1)[j], ((__half2*)&u2)[j]);
                    float2 f = __half22float2(hh);
                    h[2*j] = f.x; h[2*j+1] = f.y;
                }
                float r = 0.f;
#pragma unroll
                for (int c8 = 0; c8 < 8; c8++) {
                    float hv = h[c8];
                    hv = fmaf(a.x, w1a[0][c8], hv);
                    hv = fmaf(a.y, w1a[1][c8], hv);
                    hv = fmaf(a.z, w1a[2][c8], hv);
                    hv = fmaf(a.w, w1a[3][c8], hv);
                    float t = fmaf(Av[c8], hv, Bv[c8]);
                    t = (t >= 0.f) ? t : 0.2f * t;
                    r = fmaf(t, w2v[c8], r);
                }
#pragma unroll
                for (int o = 8; o > 0; o >>= 1)
                    r += __shfl_xor_sync(FULL, r, o);
                if (sub == 0 && (i2 + hf) < cnt) obuf[wrp][i2 + hf] = r + b2v;
            }
            __syncwarp();
            if (lane < cnt) out[ebase + lane] = obuf[wrp][lane];
            __syncwarp();
        }
    }
}

extern "C" void kernel_launch(void* const* d_in, const int* in_sizes, int n_in,
                              void* d_out, int out_size)
{
    const float* z     = (const float*)d_in[0];
    const float* ea    = (const float*)d_in[1];
    const float* W1    = (const float*)d_in[2];
    const float* gamma = (const float*)d_in[4];
    const float* beta  = (const float*)d_in[5];
    const float* W2    = (const float*)d_in[6];
    const float* b2    = (const float*)d_in[7];
    const int*   eidx  = (const int*)d_in[8];     // int32 (JAX x64 disabled)

    const int E  = in_sizes[1] / 4;   // edge_attr is [E,4]
    const int BN = in_sizes[0] / 64;  // z is [B, N, 64]
    const int Bm1 = BN / 2048 - 1;
    float* out = (float*)d_out;

    cudaFuncSetAttribute(node_gemm_kernel,
                         cudaFuncAttributeMaxDynamicSharedMemorySize, NG_SMEM);

    init_stats_kernel<<<1, 128>>>();
    node_gemm_kernel<<<(BN + 63) / 64, 256, NG_SMEM>>>(z, W1, BN);
    pass_a_kernel<<<1184, 256>>>(ea, W1, eidx, E, Bm1);
    finalize_stats_kernel<<<1, 128>>>(gamma, beta, 1.0f / (float)E);
    pass_b_kernel<<<1184, 256>>>(ea, W1, eidx, W2, b2, out, E, Bm1);
}

// round 10
// speedup vs baseline: 11.0240x; 1.2626x over previous
#include <cuda_runtime.h>
#include <cuda_fp16.h>
#include <math.h>

#define H 128
#define NMASK 2047           // N = 2048
#define BN_MAX 65536
#define FULL 0xffffffffu

__device__ __half g_P[(size_t)BN_MAX * 256];
__device__ float g_sum[H];
__device__ float g_sq[H];
__device__ float g_A[H];
__device__ float g_B[H];

__device__ __forceinline__ unsigned long long pk2(float a, float b) {
    unsigned long long r;
    asm("mov.b64 %0, {%1, %2};" : "=l"(r) : "f"(a), "f"(b));
    return r;
}
__device__ __forceinline__ void upk2(unsigned long long v, float& a, float& b) {
    asm("mov.b64 {%0, %1}, %2;" : "=f"(a), "=f"(b) : "l"(v));
}
__device__ __forceinline__ unsigned long long fma2(unsigned long long a,
                                                   unsigned long long b,
                                                   unsigned long long c) {
    unsigned long long d;
    asm("fma.rn.f32x2 %0, %1, %2, %3;" : "=l"(d) : "l"(a), "l"(b), "l"(c));
    return d;
}

__global__ void init_stats_kernel() {
    int t = threadIdx.x;
    if (t < H) { g_sum[t] = 0.f; g_sq[t] = 0.f; }
}

// ---------------- node GEMM: P[BN,256] = zf[BN,64] @ Wc[64,256], f32x2 math, fp16 out ----------------
#define NG_SMEM ((64*256 + 64*64) * 4)
__global__ void __launch_bounds__(256) node_gemm_kernel(
    const float* __restrict__ zf,   // [BN, 64]
    const float* __restrict__ W1,   // [132, 128]
    int BN)
{
    extern __shared__ float smem[];
    float* Wc = smem;               // [64][256]
    float* xs = smem + 64 * 256;    // [64 nodes][64 k]

    const int tid = threadIdx.x;
    const int nb = blockIdx.x * 64;

    const float4* W1f4 = (const float4*)W1;   // row = 32 float4
#pragma unroll
    for (int it = 0; it < 16; it++) {
        int i = tid + it * 256;
        int k = i >> 6, c4 = i & 63;
        ((float4*)Wc)[i] = (c4 < 32) ? W1f4[k * 32 + c4]
                                     : W1f4[(64 + k) * 32 + (c4 - 32)];
    }
#pragma unroll
    for (int it = 0; it < 4; it++) {
        int i = tid + it * 256;
        int node = i >> 4, k4 = i & 15;
        int nn = min(nb + node, BN - 1);
        ((float4*)xs)[node * 16 + k4] = *(const float4*)&zf[(size_t)nn * 64 + k4 * 4];
    }
    __syncthreads();

    const int cg = tid & 31;
    const int ng = tid >> 5;
    const int c0 = cg * 4;
    const int c1 = 128 + cg * 4;

    // acc2[node][colpair]: pairs (c0,c0+1)(c0+2,c0+3)(c1,c1+1)(c1+2,c1+3)
    unsigned long long acc2[8][4];
    const unsigned long long z64 = pk2(0.f, 0.f);
#pragma unroll
    for (int i = 0; i < 8; i++)
#pragma unroll
        for (int j = 0; j < 4; j++) acc2[i][j] = z64;

#pragma unroll 4
    for (int k = 0; k < 64; k++) {
        const float4 w0 = *(const float4*)&Wc[k * 256 + c0];
        const float4 w1 = *(const float4*)&Wc[k * 256 + c1];
        unsigned long long wp[4];
        wp[0] = pk2(w0.x, w0.y); wp[1] = pk2(w0.z, w0.w);
        wp[2] = pk2(w1.x, w1.y); wp[3] = pk2(w1.z, w1.w);
#pragma unroll
        for (int i = 0; i < 8; i++) {
            float xk = xs[(ng * 8 + i) * 64 + k];
            unsigned long long xk2 = pk2(xk, xk);
#pragma unroll
            for (int j = 0; j < 4; j++)
                acc2[i][j] = fma2(xk2, wp[j], acc2[i][j]);
        }
    }

#pragma unroll
    for (int i = 0; i < 8; i++) {
        int node = nb + ng * 8 + i;
        if (node < BN) {
            float a0, a1, a2, a3, a4, a5, a6, a7;
            upk2(acc2[i][0], a0, a1); upk2(acc2[i][1], a2, a3);
            upk2(acc2[i][2], a4, a5); upk2(acc2[i][3], a6, a7);
            *(__half2*)&g_P[(size_t)node * 256 + c0]     = __floats2half2_rn(a0, a1);
            *(__half2*)&g_P[(size_t)node * 256 + c0 + 2] = __floats2half2_rn(a2, a3);
            *(__half2*)&g_P[(size_t)node * 256 + c1]     = __floats2half2_rn(a4, a5);
            *(__half2*)&g_P[(size_t)node * 256 + c1 + 2] = __floats2half2_rn(a6, a7);
        }
    }
}

// ---------------- pass A: 2 edges/warp, half2 math, BN stats over h' (no b1) ----------------
__global__ void __launch_bounds__(256, 3) pass_a_kernel(
    const float* __restrict__ ea,   // [E,4]
    const float* __restrict__ W1,   // [132,128]
    const int* __restrict__ eidx,   // [2,E] int32
    int E, int Bm1)
{
    __shared__ float bsum[H], bsq[H];
    const int tid  = threadIdx.x;
    const int lane = tid & 31;
    const int wrp  = tid >> 5;
    const int hf   = lane >> 4;
    const int sub  = lane & 15;
    const int ch   = sub * 8;
    if (tid < H) { bsum[tid] = 0.f; bsq[tid] = 0.f; }
    __syncthreads();

    __half2 w1ah[4][4];
#pragma unroll
    for (int k = 0; k < 4; k++) {
        float4 v0 = *(const float4*)&W1[(128 + k) * H + ch];
        float4 v1 = *(const float4*)&W1[(128 + k) * H + ch + 4];
        w1ah[k][0] = __floats2half2_rn(v0.x, v0.y);
        w1ah[k][1] = __floats2half2_rn(v0.z, v0.w);
        w1ah[k][2] = __floats2half2_rn(v1.x, v1.y);
        w1ah[k][3] = __floats2half2_rn(v1.z, v1.w);
    }

    float sacc[8], qacc[8];
#pragma unroll
    for (int j = 0; j < 8; j++) { sacc[j] = 0.f; qacc[j] = 0.f; }
    const __half2 z2 = __float2half2_rn(0.f);

    const int nwarps = gridDim.x * 8;
    const int gw = blockIdx.x * 8 + wrp;
    const int nchunks = (E + 31) >> 5;

    for (int chk = gw; chk < nchunks; chk += nwarps) {
        const int ebase = chk << 5;
        int e_l = ebase + lane;
        int s = 0, d = 0;
        if (e_l < E) { s = eidx[e_l]; d = eidx[(size_t)E + e_l]; }
        int batch = min(max(s >> 11, 0), Bm1);
        int off = batch << 11;
        int si = (s & NMASK) + off;
        int di = (d & NMASK) + off;

        __half2 sum2[4] = {z2, z2, z2, z2};
        __half2 sq2[4]  = {z2, z2, z2, z2};

        if (ebase + 32 <= E) {
#pragma unroll 1
            for (int ii = 0; ii < 16; ii += 2) {
                uint4 u1[2], u2[2]; float4 av[2];
#pragma unroll
                for (int b = 0; b < 2; b++) {
                    int srcl = 2 * (ii + b) + hf;
                    int sii = __shfl_sync(FULL, si, srcl);
                    int dii = __shfl_sync(FULL, di, srcl);
                    u1[b] = *(const uint4*)&g_P[(size_t)sii * 256 + ch];
                    u2[b] = *(const uint4*)&g_P[(size_t)dii * 256 + 128 + ch];
                    av[b] = *(const float4*)&ea[(size_t)(ebase + srcl) * 4];
                }
#pragma unroll
                for (int b = 0; b < 2; b++) {
                    __half2 a0 = __floats2half2_rn(av[b].x, av[b].x);
                    __half2 a1 = __floats2half2_rn(av[b].y, av[b].y);
                    __half2 a2 = __floats2half2_rn(av[b].z, av[b].z);
                    __half2 a3 = __floats2half2_rn(av[b].w, av[b].w);
#pragma unroll
                    for (int j = 0; j < 4; j++) {
                        __half2 hh = __hadd2(((__half2*)&u1[b])[j], ((__half2*)&u2[b])[j]);
                        hh = __hfma2(a0, w1ah[0][j], hh);
                        hh = __hfma2(a1, w1ah[1][j], hh);
                        hh = __hfma2(a2, w1ah[2][j], hh);
                        hh = __hfma2(a3, w1ah[3][j], hh);
                        sum2[j] = __hadd2(sum2[j], hh);
                        sq2[j]  = __hfma2(hh, hh, sq2[j]);
                    }
                }
            }
        } else {
            const int cnt = E - ebase;
            for (int i2 = 0; i2 < cnt; i2 += 2) {
                int srcl = min(i2 + hf, cnt - 1);
                int sii = __shfl_sync(FULL, si, srcl);
                int dii = __shfl_sync(FULL, di, srcl);
                uint4 u1 = *(const uint4*)&g_P[(size_t)sii * 256 + ch];
                uint4 u2 = *(const uint4*)&g_P[(size_t)dii * 256 + 128 + ch];
                float4 a = *(const float4*)&ea[(size_t)(ebase + srcl) * 4];
                if (i2 + hf < cnt) {
                    __half2 a0 = __floats2half2_rn(a.x, a.x);
                    __half2 a1 = __floats2half2_rn(a.y, a.y);
                    __half2 a2 = __floats2half2_rn(a.z, a.z);
                    __half2 a3 = __floats2half2_rn(a.w, a.w);
#pragma unroll
                    for (int j = 0; j < 4; j++) {
                        __half2 hh = __hadd2(((__half2*)&u1)[j], ((__half2*)&u2)[j]);
                        hh = __hfma2(a0, w1ah[0][j], hh);
                        hh = __hfma2(a1, w1ah[1][j], hh);
                        hh = __hfma2(a2, w1ah[2][j], hh);
                        hh = __hfma2(a3, w1ah[3][j], hh);
                        sum2[j] = __hadd2(sum2[j], hh);
                        sq2[j]  = __hfma2(hh, hh, sq2[j]);
                    }
                }
            }
        }
#pragma unroll
        for (int j = 0; j < 4; j++) {
            float2 fs = __half22float2(sum2[j]);
            float2 fq = __half22float2(sq2[j]);
            sacc[2*j]   += fs.x; sacc[2*j+1] += fs.y;
            qacc[2*j]   += fq.x; qacc[2*j+1] += fq.y;
        }
    }

#pragma unroll
    for (int j = 0; j < 8; j++) {
        atomicAdd(&bsum[ch + j], sacc[j]);
        atomicAdd(&bsq [ch + j], qacc[j]);
    }
    __syncthreads();
    if (tid < H) {
        atomicAdd(&g_sum[tid], bsum[tid]);
        atomicAdd(&g_sq[tid],  bsq[tid]);
    }
}

// stats over h' = h - b1: var(h)=var(h'), b1 absorbed into B_fold.
__global__ void finalize_stats_kernel(const float* __restrict__ gamma,
                                      const float* __restrict__ beta,
                                      float invE)
{
    int c = threadIdx.x;
    if (c < H) {
        float mup = g_sum[c] * invE;
        float var = g_sq[c] * invE - mup * mup;
        float inv = rsqrtf(var + 1e-5f);
        float A = gamma[c] * inv;
        g_A[c] = A;
        g_B[c] = beta[c] - mup * A;
    }
}

// ---------------- pass B: 2 edges/warp, half2 attr term, fp32 affine/dot ----------------
__global__ void __launch_bounds__(256, 3) pass_b_kernel(
    const float* __restrict__ ea,
    const float* __restrict__ W1,
    const int* __restrict__ eidx,
    const float* __restrict__ W2,   // [128]
    const float* __restrict__ b2,   // [1]
    float* __restrict__ out,        // [E]
    int E, int Bm1)
{
    __shared__ float obuf[8][32];
    const int tid  = threadIdx.x;
    const int lane = tid & 31;
    const int wrp  = tid >> 5;
    const int hf   = lane >> 4;
    const int sub  = lane & 15;
    const int ch   = sub * 8;

    __half2 w1ah[4][4];
#pragma unroll
    for (int k = 0; k < 4; k++) {
        float4 v0 = *(const float4*)&W1[(128 + k) * H + ch];
        float4 v1 = *(const float4*)&W1[(128 + k) * H + ch + 4];
        w1ah[k][0] = __floats2half2_rn(v0.x, v0.y);
        w1ah[k][1] = __floats2half2_rn(v0.z, v0.w);
        w1ah[k][2] = __floats2half2_rn(v1.x, v1.y);
        w1ah[k][3] = __floats2half2_rn(v1.z, v1.w);
    }
    float Av[8], Bv[8], w2v[8];
    {
        float4 t0 = *(const float4*)&g_A[ch];  float4 t1 = *(const float4*)&g_A[ch+4];
        Av[0]=t0.x; Av[1]=t0.y; Av[2]=t0.z; Av[3]=t0.w; Av[4]=t1.x; Av[5]=t1.y; Av[6]=t1.z; Av[7]=t1.w;
        float4 u0 = *(const float4*)&g_B[ch];  float4 u1 = *(const float4*)&g_B[ch+4];
        Bv[0]=u0.x; Bv[1]=u0.y; Bv[2]=u0.z; Bv[3]=u0.w; Bv[4]=u1.x; Bv[5]=u1.y; Bv[6]=u1.z; Bv[7]=u1.w;
        float4 s0 = *(const float4*)&W2[ch];   float4 s1 = *(const float4*)&W2[ch+4];
        w2v[0]=s0.x; w2v[1]=s0.y; w2v[2]=s0.z; w2v[3]=s0.w; w2v[4]=s1.x; w2v[5]=s1.y; w2v[6]=s1.z; w2v[7]=s1.w;
    }
    const float b2v = b2[0];

    const int nwarps = gridDim.x * 8;
    const int gw = blockIdx.x * 8 + wrp;
    const int nchunks = (E + 31) >> 5;

    for (int chk = gw; chk < nchunks; chk += nwarps) {
        const int ebase = chk << 5;
        int e_l = ebase + lane;
        int s = 0, d = 0;
        if (e_l < E) { s = eidx[e_l]; d = eidx[(size_t)E + e_l]; }
        int batch = min(max(s >> 11, 0), Bm1);
        int off = batch << 11;
        int si = (s & NMASK) + off;
        int di = (d & NMASK) + off;

        if (ebase + 32 <= E) {
#pragma unroll 1
            for (int ii = 0; ii < 16; ii += 2) {
                uint4 u1[2], u2[2]; float4 av[2];
#pragma unroll
                for (int b = 0; b < 2; b++) {
                    int srcl = 2 * (ii + b) + hf;
                    int sii = __shfl_sync(FULL, si, srcl);
                    int dii = __shfl_sync(FULL, di, srcl);
                    u1[b] = *(const uint4*)&g_P[(size_t)sii * 256 + ch];
                    u2[b] = *(const uint4*)&g_P[(size_t)dii * 256 + 128 + ch];
                    av[b] = *(const float4*)&ea[(size_t)(ebase + srcl) * 4];
                }
#pragma unroll
                for (int b = 0; b < 2; b++) {
                    __half2 a0 = __floats2half2_rn(av[b].x, av[b].x);
                    __half2 a1 = __floats2half2_rn(av[b].y, av[b].y);
                    __half2 a2 = __floats2half2_rn(av[b].z, av[b].z);
                    __half2 a3 = __floats2half2_rn(av[b].w, av[b].w);
                    float r = 0.f;
#pragma unroll
                    for (int j = 0; j < 4; j++) {
                        __half2 hh = __hadd2(((__half2*)&u1[b])[j], ((__half2*)&u2[b])[j]);
                        hh = __hfma2(a0, w1ah[0][j], hh);
                        hh = __hfma2(a1, w1ah[1][j], hh);
                        hh = __hfma2(a2, w1ah[2][j], hh);
                        hh = __hfma2(a3, w1ah[3][j], hh);
                        float2 f = __half22float2(hh);
                        float t0 = fmaf(Av[2*j],   f.x, Bv[2*j]);
                        float t1 = fmaf(Av[2*j+1], f.y, Bv[2*j+1]);
                        t0 = (t0 >= 0.f) ? t0 : 0.2f * t0;
                        t1 = (t1 >= 0.f) ? t1 : 0.2f * t1;
                        r = fmaf(t0, w2v[2*j], r);
                        r = fmaf(t1, w2v[2*j+1], r);
                    }
#pragma unroll
                    for (int o = 8; o > 0; o >>= 1)
                        r += __shfl_xor_sync(FULL, r, o);
                    if (sub == 0) obuf[wrp][2 * (ii + b) + hf] = r + b2v;
                }
            }
            __syncwarp();
            out[ebase + lane] = obuf[wrp][lane];
            __syncwarp();
        } else {
            const int cnt = E - ebase;
            for (int i2 = 0; i2 < cnt; i2 += 2) {
                int srcl = min(i2 + hf, cnt - 1);
                int sii = __shfl_sync(FULL, si, srcl);
                int dii = __shfl_sync(FULL, di, srcl);
                uint4 u1 = *(const uint4*)&g_P[(size_t)sii * 256 + ch];
                uint4 u2 = *(const uint4*)&g_P[(size_t)dii * 256 + 128 + ch];
                float4 a = *(const float4*)&ea[(size_t)(ebase + srcl) * 4];
                __half2 a0 = __floats2half2_rn(a.x, a.x);
                __half2 a1 = __floats2half2_rn(a.y, a.y);
                __half2 a2 = __floats2half2_rn(a.z, a.z);
                __half2 a3 = __floats2half2_rn(a.w, a.w);
                float r = 0.f;
#pragma unroll
                for (int j = 0; j < 4; j++) {
                    __half2 hh = __hadd2(((__half2*)&u1)[j], ((__half2*)&u2)[j]);
                    hh = __hfma2(a0, w1ah[0][j], hh);
                    hh = __hfma2(a1, w1ah[1][j], hh);
                    hh = __hfma2(a2, w1ah[2][j], hh);
                    hh = __hfma2(a3, w1ah[3][j], hh);
                    float2 f = __half22float2(hh);
                    float t0 = fmaf(Av[2*j],   f.x, Bv[2*j]);
                    float t1 = fmaf(Av[2*j+1], f.y, Bv[2*j+1]);
                    t0 = (t0 >= 0.f) ? t0 : 0.2f * t0;
                    t1 = (t1 >= 0.f) ? t1 : 0.2f * t1;
                    r = fmaf(t0, w2v[2*j], r);
                    r = fmaf(t1, w2v[2*j+1], r);
                }
#pragma unroll
                for (int o = 8; o > 0; o >>= 1)
                    r += __shfl_xor_sync(FULL, r, o);
                if (sub == 0 && (i2 + hf) < cnt) obuf[wrp][i2 + hf] = r + b2v;
            }
            __syncwarp();
            if (lane < cnt) out[ebase + lane] = obuf[wrp][lane];
            __syncwarp();
        }
    }
}

extern "C" void kernel_launch(void* const* d_in, const int* in_sizes, int n_in,
                              void* d_out, int out_size)
{
    const float* z     = (const float*)d_in[0];
    const float* ea    = (const float*)d_in[1];
    const float* W1    = (const float*)d_in[2];
    const float* gamma = (const float*)d_in[4];
    const float* beta  = (const float*)d_in[5];
    const float* W2    = (const float*)d_in[6];
    const float* b2    = (const float*)d_in[7];
    const int*   eidx  = (const int*)d_in[8];     // int32 (JAX x64 disabled)

    const int E  = in_sizes[1] / 4;   // edge_attr is [E,4]
    const int BN = in_sizes[0] / 64;  // z is [B, N, 64]
    const int Bm1 = BN / 2048 - 1;
    float* out = (float*)d_out;

    cudaFuncSetAttribute(node_gemm_kernel,
                         cudaFuncAttributeMaxDynamicSharedMemorySize, NG_SMEM);

    init_stats_kernel<<<1, 128>>>();
    node_gemm_kernel<<<(BN + 63) / 64, 256, NG_SMEM>>>(z, W1, BN);
    pass_a_kernel<<<888, 256>>>(ea, W1, eidx, E, Bm1);
    finalize_stats_kernel<<<1, 128>>>(gamma, beta, 1.0f / (float)E);
    pass_b_kernel<<<888, 256>>>(ea, W1, eidx, W2, b2, out, E, Bm1);
}